// round 9
// baseline (speedup 1.0000x reference)
#include <cuda_runtime.h>

// 4-level 2D Haar DWT, fully fused, persistent grid-stride form.
// R2 structure (best: 66.3us ncu) with a 1-wave persistent grid:
// 1184 blocks (148 SM x 8 resident), each looping over ~10 of the 12288
// 64x64 tiles. Removes wave-transition + per-block start overhead and lets
// next-tile loads overlap previous-tile store drain. No cache hints
// (all hint variants measured as regressions in R3/R6).
//
// Input : x (64, 3, 512, 512) f32 -> 192 images of 512x512
// Output: concat of levels l=0..3, each (192, 4, S, S), S = 256 >> l
//   subband order: 0=cA, 1=cH, 2=cV, 3=cD

#define NIMG 192
#define HW   512
#define NTILES (NIMG * 64)     // 12288 tiles of 64x64
#define GRIDB  1184            // 148 SMs x 8 blocks

#define OFF0 0ull
#define OFF1 (OFF0 + (unsigned long long)NIMG * 4ull * 256ull * 256ull)
#define OFF2 (OFF1 + (unsigned long long)NIMG * 4ull * 128ull * 128ull)
#define OFF3 (OFF2 + (unsigned long long)NIMG * 4ull *  64ull *  64ull)

#define HAAR(a, b, c, d, cA, cH, cV, cD)                    \
    do {                                                    \
        float _hs0 = (a) + (b), _hd0 = (a) - (b);           \
        float _hs1 = (c) + (d), _hd1 = (c) - (d);           \
        (cA) = (_hs0 + _hs1) * 0.5f;                        \
        (cH) = (_hs0 - _hs1) * 0.5f;                        \
        (cV) = (_hd0 + _hd1) * 0.5f;                        \
        (cD) = (_hd0 - _hd1) * 0.5f;                        \
    } while (0)

__global__ __launch_bounds__(256) void fwt_kernel(const float* __restrict__ x,
                                                  float* __restrict__ out) {
    const int tid = threadIdx.x;

    __shared__ float sB[32][33];  // level-0 cA
    __shared__ float sC[16][17];  // level-1 cA
    __shared__ float sD[8][9];    // level-2 cA

    for (int tile = blockIdx.x; tile < NTILES; tile += GRIDB) {
        const int img = tile >> 6;          // tile / 64
        const int rem = tile & 63;
        const int ty  = rem >> 3;           // 0..7
        const int tx  = rem & 7;            // 0..7

        // ---- level 0: direct global -> registers -> global, S=256 ----
        {
            const int qi  = tid >> 3;   // 0..31 quad row
            const int qjg = tid & 7;    // group of 4 quads -> input cols qjg*8..+7

            const float* src = x + ((size_t)img * HW + (size_t)ty * 64 + 2 * qi) * HW
                                 + (size_t)tx * 64 + qjg * 8;
            const float4 r0a = *reinterpret_cast<const float4*>(src);
            const float4 r0b = *reinterpret_cast<const float4*>(src + 4);
            const float4 r1a = *reinterpret_cast<const float4*>(src + HW);
            const float4 r1b = *reinterpret_cast<const float4*>(src + HW + 4);

            float4 cA4, cH4, cV4, cD4;
            HAAR(r0a.x, r0a.y, r1a.x, r1a.y, cA4.x, cH4.x, cV4.x, cD4.x);
            HAAR(r0a.z, r0a.w, r1a.z, r1a.w, cA4.y, cH4.y, cV4.y, cD4.y);
            HAAR(r0b.x, r0b.y, r1b.x, r1b.y, cA4.z, cH4.z, cV4.z, cD4.z);
            HAAR(r0b.z, r0b.w, r1b.z, r1b.w, cA4.w, cH4.w, cV4.w, cD4.w);

            const int S = 256;
            float* base = out + OFF0 + (size_t)img * 4ull * S * S;
            const int gi = ty * 32 + qi, gj = tx * 32 + qjg * 4;
            const size_t o = (size_t)gi * S + gj;
            *reinterpret_cast<float4*>(base + o)                 = cA4;
            *reinterpret_cast<float4*>(base + (size_t)S * S + o) = cH4;
            *reinterpret_cast<float4*>(base + 2ull * S * S + o)  = cV4;
            *reinterpret_cast<float4*>(base + 3ull * S * S + o)  = cD4;

            sB[qi][qjg * 4 + 0] = cA4.x;
            sB[qi][qjg * 4 + 1] = cA4.y;
            sB[qi][qjg * 4 + 2] = cA4.z;
            sB[qi][qjg * 4 + 3] = cA4.w;
        }
        __syncthreads();

        // ---- level 1: 32x32 -> 16x16, S=128 (64 threads x 4 quads) ----
        if (tid < 64) {
            const int qi  = tid >> 2;   // 0..15
            const int qjg = tid & 3;    // cols qjg*8..+7 of sB

            float4 cA4, cH4, cV4, cD4;
            {
                const int r0 = 2 * qi, r1 = 2 * qi + 1, c0 = qjg * 8;
                HAAR(sB[r0][c0 + 0], sB[r0][c0 + 1], sB[r1][c0 + 0], sB[r1][c0 + 1],
                     cA4.x, cH4.x, cV4.x, cD4.x);
                HAAR(sB[r0][c0 + 2], sB[r0][c0 + 3], sB[r1][c0 + 2], sB[r1][c0 + 3],
                     cA4.y, cH4.y, cV4.y, cD4.y);
                HAAR(sB[r0][c0 + 4], sB[r0][c0 + 5], sB[r1][c0 + 4], sB[r1][c0 + 5],
                     cA4.z, cH4.z, cV4.z, cD4.z);
                HAAR(sB[r0][c0 + 6], sB[r0][c0 + 7], sB[r1][c0 + 6], sB[r1][c0 + 7],
                     cA4.w, cH4.w, cV4.w, cD4.w);
            }

            const int S = 128;
            float* base = out + OFF1 + (size_t)img * 4ull * S * S;
            const int gi = ty * 16 + qi, gj = tx * 16 + qjg * 4;
            const size_t o = (size_t)gi * S + gj;
            *reinterpret_cast<float4*>(base + o)                 = cA4;
            *reinterpret_cast<float4*>(base + (size_t)S * S + o) = cH4;
            *reinterpret_cast<float4*>(base + 2ull * S * S + o)  = cV4;
            *reinterpret_cast<float4*>(base + 3ull * S * S + o)  = cD4;

            sC[qi][qjg * 4 + 0] = cA4.x;
            sC[qi][qjg * 4 + 1] = cA4.y;
            sC[qi][qjg * 4 + 2] = cA4.z;
            sC[qi][qjg * 4 + 3] = cA4.w;
        }
        __syncthreads();

        // ---- level 2: 16x16 -> 8x8, S=64 (16 threads x 4 quads) ----
        if (tid < 16) {
            const int qi  = tid >> 1;   // 0..7
            const int qjg = tid & 1;    // cols qjg*8..+7 of sC

            float4 cA4, cH4, cV4, cD4;
            {
                const int r0 = 2 * qi, r1 = 2 * qi + 1, c0 = qjg * 8;
                HAAR(sC[r0][c0 + 0], sC[r0][c0 + 1], sC[r1][c0 + 0], sC[r1][c0 + 1],
                     cA4.x, cH4.x, cV4.x, cD4.x);
                HAAR(sC[r0][c0 + 2], sC[r0][c0 + 3], sC[r1][c0 + 2], sC[r1][c0 + 3],
                     cA4.y, cH4.y, cV4.y, cD4.y);
                HAAR(sC[r0][c0 + 4], sC[r0][c0 + 5], sC[r1][c0 + 4], sC[r1][c0 + 5],
                     cA4.z, cH4.z, cV4.z, cD4.z);
                HAAR(sC[r0][c0 + 6], sC[r0][c0 + 7], sC[r1][c0 + 6], sC[r1][c0 + 7],
                     cA4.w, cH4.w, cV4.w, cD4.w);
            }

            const int S = 64;
            float* base = out + OFF2 + (size_t)img * 4ull * S * S;
            const int gi = ty * 8 + qi, gj = tx * 8 + qjg * 4;
            const size_t o = (size_t)gi * S + gj;
            *reinterpret_cast<float4*>(base + o)                 = cA4;
            *reinterpret_cast<float4*>(base + (size_t)S * S + o) = cH4;
            *reinterpret_cast<float4*>(base + 2ull * S * S + o)  = cV4;
            *reinterpret_cast<float4*>(base + 3ull * S * S + o)  = cD4;

            sD[qi][qjg * 4 + 0] = cA4.x;
            sD[qi][qjg * 4 + 1] = cA4.y;
            sD[qi][qjg * 4 + 2] = cA4.z;
            sD[qi][qjg * 4 + 3] = cA4.w;
        }
        __syncthreads();

        // ---- level 3: 8x8 -> 4x4, S=32 (4 threads x 4 quads) ----
        if (tid < 4) {
            const int qi = tid;  // 0..3, full 4-quad row

            float4 cA4, cH4, cV4, cD4;
            {
                const int r0 = 2 * qi, r1 = 2 * qi + 1;
                HAAR(sD[r0][0], sD[r0][1], sD[r1][0], sD[r1][1], cA4.x, cH4.x, cV4.x, cD4.x);
                HAAR(sD[r0][2], sD[r0][3], sD[r1][2], sD[r1][3], cA4.y, cH4.y, cV4.y, cD4.y);
                HAAR(sD[r0][4], sD[r0][5], sD[r1][4], sD[r1][5], cA4.z, cH4.z, cV4.z, cD4.z);
                HAAR(sD[r0][6], sD[r0][7], sD[r1][6], sD[r1][7], cA4.w, cH4.w, cV4.w, cD4.w);
            }

            const int S = 32;
            float* base = out + OFF3 + (size_t)img * 4ull * S * S;
            const int gi = ty * 4 + qi, gj = tx * 4;
            const size_t o = (size_t)gi * S + gj;
            *reinterpret_cast<float4*>(base + o)                 = cA4;
            *reinterpret_cast<float4*>(base + (size_t)S * S + o) = cH4;
            *reinterpret_cast<float4*>(base + 2ull * S * S + o)  = cV4;
            *reinterpret_cast<float4*>(base + 3ull * S * S + o)  = cD4;
        }
        // no extra sync needed: next-iteration sB writes are ordered behind
        // this iteration's L2->L3 barrier; sD readers (tid<4) gate the next
        // iteration's first barrier.
    }
}

extern "C" void kernel_launch(void* const* d_in, const int* in_sizes, int n_in,
                              void* d_out, int out_size) {
    const float* x = (const float*)d_in[0];
    float* out     = (float*)d_out;
    fwt_kernel<<<GRIDB, 256>>>(x, out);
}

// round 10
// speedup vs baseline: 1.0999x; 1.0999x over previous
#include <cuda_runtime.h>

// 4-level 2D Haar DWT, fully fused, register-level level-0 (R2 structure,
// best measured). Levels 1-3 now use maximal thread width (1 quad/thread)
// to minimize the per-block tail critical path:
//   L1: 256 quads -> 256 threads, L2: 64 quads -> 64 threads, L3: 16 -> 16.
// No cache hints (all variants measured as regressions). Grid (8,8,192).
//
// Input : x (64, 3, 512, 512) f32 -> 192 images of 512x512
// Output: concat of levels l=0..3, each (192, 4, S, S), S = 256 >> l
//   subband order: 0=cA, 1=cH, 2=cV, 3=cD

#define NIMG 192
#define HW   512

#define OFF0 0ull
#define OFF1 (OFF0 + (unsigned long long)NIMG * 4ull * 256ull * 256ull)
#define OFF2 (OFF1 + (unsigned long long)NIMG * 4ull * 128ull * 128ull)
#define OFF3 (OFF2 + (unsigned long long)NIMG * 4ull *  64ull *  64ull)

#define HAAR(a, b, c, d, cA, cH, cV, cD)                    \
    do {                                                    \
        float _hs0 = (a) + (b), _hd0 = (a) - (b);           \
        float _hs1 = (c) + (d), _hd1 = (c) - (d);           \
        (cA) = (_hs0 + _hs1) * 0.5f;                        \
        (cH) = (_hs0 - _hs1) * 0.5f;                        \
        (cV) = (_hd0 + _hd1) * 0.5f;                        \
        (cD) = (_hd0 - _hd1) * 0.5f;                        \
    } while (0)

__global__ __launch_bounds__(256) void fwt_kernel(const float* __restrict__ x,
                                                  float* __restrict__ out) {
    const int img = blockIdx.z;
    const int ty  = blockIdx.y;
    const int tx  = blockIdx.x;
    const int tid = threadIdx.x;

    __shared__ float sB[32][33];  // level-0 cA
    __shared__ float sC[16][17];  // level-1 cA
    __shared__ float sD[8][9];    // level-2 cA

    // ---- level 0: direct global -> registers -> global, S=256 ----
    {
        const int qi  = tid >> 3;   // 0..31 quad row
        const int qjg = tid & 7;    // group of 4 quads -> input cols qjg*8..+7

        const float* src = x + ((size_t)img * HW + (size_t)ty * 64 + 2 * qi) * HW
                             + (size_t)tx * 64 + qjg * 8;
        const float4 r0a = *reinterpret_cast<const float4*>(src);
        const float4 r0b = *reinterpret_cast<const float4*>(src + 4);
        const float4 r1a = *reinterpret_cast<const float4*>(src + HW);
        const float4 r1b = *reinterpret_cast<const float4*>(src + HW + 4);

        float4 cA4, cH4, cV4, cD4;
        HAAR(r0a.x, r0a.y, r1a.x, r1a.y, cA4.x, cH4.x, cV4.x, cD4.x);
        HAAR(r0a.z, r0a.w, r1a.z, r1a.w, cA4.y, cH4.y, cV4.y, cD4.y);
        HAAR(r0b.x, r0b.y, r1b.x, r1b.y, cA4.z, cH4.z, cV4.z, cD4.z);
        HAAR(r0b.z, r0b.w, r1b.z, r1b.w, cA4.w, cH4.w, cV4.w, cD4.w);

        const int S = 256;
        float* base = out + OFF0 + (size_t)img * 4ull * S * S;
        const int gi = ty * 32 + qi, gj = tx * 32 + qjg * 4;
        const size_t o = (size_t)gi * S + gj;
        *reinterpret_cast<float4*>(base + o)                 = cA4;
        *reinterpret_cast<float4*>(base + (size_t)S * S + o) = cH4;
        *reinterpret_cast<float4*>(base + 2ull * S * S + o)  = cV4;
        *reinterpret_cast<float4*>(base + 3ull * S * S + o)  = cD4;

        sB[qi][qjg * 4 + 0] = cA4.x;
        sB[qi][qjg * 4 + 1] = cA4.y;
        sB[qi][qjg * 4 + 2] = cA4.z;
        sB[qi][qjg * 4 + 3] = cA4.w;
    }
    __syncthreads();

    // ---- level 1: 32x32 -> 16x16 quads, S=128 (256 threads x 1 quad) ----
    {
        const int qi = tid >> 4;    // 0..15
        const int qj = tid & 15;    // 0..15

        float cAv, cHv, cVv, cDv;
        HAAR(sB[2 * qi][2 * qj], sB[2 * qi][2 * qj + 1],
             sB[2 * qi + 1][2 * qj], sB[2 * qi + 1][2 * qj + 1],
             cAv, cHv, cVv, cDv);

        const int S = 128;
        float* base = out + OFF1 + (size_t)img * 4ull * S * S;
        const int gi = ty * 16 + qi, gj = tx * 16 + qj;
        const size_t o = (size_t)gi * S + gj;
        base[o]                 = cAv;
        base[(size_t)S * S + o] = cHv;
        base[2ull * S * S + o]  = cVv;
        base[3ull * S * S + o]  = cDv;

        sC[qi][qj] = cAv;
    }
    __syncthreads();

    // ---- level 2: 16x16 -> 8x8 quads, S=64 (64 threads x 1 quad) ----
    if (tid < 64) {
        const int qi = tid >> 3;    // 0..7
        const int qj = tid & 7;     // 0..7

        float cAv, cHv, cVv, cDv;
        HAAR(sC[2 * qi][2 * qj], sC[2 * qi][2 * qj + 1],
             sC[2 * qi + 1][2 * qj], sC[2 * qi + 1][2 * qj + 1],
             cAv, cHv, cVv, cDv);

        const int S = 64;
        float* base = out + OFF2 + (size_t)img * 4ull * S * S;
        const int gi = ty * 8 + qi, gj = tx * 8 + qj;
        const size_t o = (size_t)gi * S + gj;
        base[o]                 = cAv;
        base[(size_t)S * S + o] = cHv;
        base[2ull * S * S + o]  = cVv;
        base[3ull * S * S + o]  = cDv;

        sD[qi][qj] = cAv;
    }
    __syncthreads();

    // ---- level 3: 8x8 -> 4x4 quads, S=32 (16 threads x 1 quad) ----
    if (tid < 16) {
        const int qi = tid >> 2;    // 0..3
        const int qj = tid & 3;     // 0..3

        float cAv, cHv, cVv, cDv;
        HAAR(sD[2 * qi][2 * qj], sD[2 * qi][2 * qj + 1],
             sD[2 * qi + 1][2 * qj], sD[2 * qi + 1][2 * qj + 1],
             cAv, cHv, cVv, cDv);

        const int S = 32;
        float* base = out + OFF3 + (size_t)img * 4ull * S * S;
        const int gi = ty * 4 + qi, gj = tx * 4 + qj;
        const size_t o = (size_t)gi * S + gj;
        base[o]                 = cAv;
        base[(size_t)S * S + o] = cHv;
        base[2ull * S * S + o]  = cVv;
        base[3ull * S * S + o]  = cDv;
    }
}

extern "C" void kernel_launch(void* const* d_in, const int* in_sizes, int n_in,
                              void* d_out, int out_size) {
    const float* x = (const float*)d_in[0];
    float* out     = (float*)d_out;
    dim3 grid(8, 8, NIMG);
    fwt_kernel<<<grid, 256>>>(x, out);
}